// round 11
// baseline (speedup 1.0000x reference)
#include <cuda_runtime.h>
#include <cuda_bf16.h>

// Fast Walsh-Hadamard transform, 16384 rows x 1024 fp32.
// y[row] = FWHT(x[row]) / 32, emitted as interleaved (real, 0) pairs.
//
// PERSISTENT pipelined kernel: grid = 6 blocks/SM (exactly one wave, no
// tail). Each warp grid-strides over rows with a 2-deep register pipeline:
// the 16 coalesced LDG.64 for the NEXT row are in flight under the current
// row's ~600-cycle shfl/FADD chain, at every iteration (no pipeline restart).
//
// Per row (one warp, 32 values/thread), lane l owns elements {2l + b + 64j}:
//   stride 1          -> register butterfly (b pair)
//   strides 2..32     -> 5 shfl.xor stages
//   strides 64..512   -> register butterflies over j bits
// No shared memory, no barriers. Stores: 16 coalesced STG.128 (__stcs, so
// the write stream doesn't evict the L2-resident input), zeros folded in.

#define DIMN 1024
#define WPB  4            // warps per block -> 128 threads
#define BPSM 6            // blocks per SM (regs ~80 -> 6*128*80 < 64K regs)

__device__ __forceinline__ void bf(float &x, float &y) {
    float s = x + y;
    y = x - y;
    x = s;
}

__global__ void __launch_bounds__(32 * WPB, BPSM)
fwht_kernel(const float2* __restrict__ xin, float4* __restrict__ yout, int nrows)
{
    const int l  = threadIdx.x & 31;
    const int w  = threadIdx.x >> 5;
    const int gw = blockIdx.x * WPB + w;          // global warp id
    const int stride = gridDim.x * WPB;           // total warps

    int row = gw;
    if (row >= nrows) return;

    // ---- prime the pipeline: 16 independent coalesced LDG.64 ----
    float2 p[16];
    {
        const float2* in = xin + (size_t)row * (DIMN / 2) + l;
        #pragma unroll
        for (int j = 0; j < 16; j++) p[j] = in[32 * j];
    }

    while (true) {
        const int next = row + stride;

        // take ownership of the prefetched row
        float a[16], b[16];
        #pragma unroll
        for (int j = 0; j < 16; j++) { a[j] = p[j].x; b[j] = p[j].y; }

        // issue next row's loads NOW; the compute below hides their latency
        if (next < nrows) {
            const float2* in = xin + (size_t)next * (DIMN / 2) + l;
            #pragma unroll
            for (int j = 0; j < 16; j++) p[j] = in[32 * j];
        }

        // ---- stride 1 (register, b-pair) ----
        #pragma unroll
        for (int j = 0; j < 16; j++) bf(a[j], b[j]);

        // ---- strides 2,4,8,16,32 via shfl.xor on lane bits ----
        #pragma unroll
        for (int d = 1; d <= 16; d <<= 1) {
            const bool up = (l & d) != 0;
            #pragma unroll
            for (int j = 0; j < 16; j++) {
                float oa = __shfl_xor_sync(0xffffffffu, a[j], d);
                float ob = __shfl_xor_sync(0xffffffffu, b[j], d);
                a[j] = up ? (oa - a[j]) : (a[j] + oa);
                b[j] = up ? (ob - b[j]) : (b[j] + ob);
            }
        }

        // ---- strides 64,128,256,512: butterflies over j bits ----
        #pragma unroll
        for (int s = 1; s <= 8; s <<= 1) {
            #pragma unroll
            for (int j = 0; j < 16; j++) {
                if ((j & s) == 0) {
                    bf(a[j], a[j + s]);
                    bf(b[j], b[j + s]);
                }
            }
        }

        // ---- scaled, interleaved (real, 0) stores; 16 coalesced STG.128 ----
        const float sc = 0.03125f;   // 1/sqrt(1024)
        float4* out = yout + (size_t)row * (2 * DIMN / 4) + l;
        #pragma unroll
        for (int j = 0; j < 16; j++) {
            __stcs(out + 32 * j, make_float4(a[j] * sc, 0.0f, b[j] * sc, 0.0f));
        }

        if (next >= nrows) break;
        row = next;
    }
}

extern "C" void kernel_launch(void* const* d_in, const int* in_sizes, int n_in,
                              void* d_out, int out_size)
{
    const float* x = (const float*)d_in[0];   // [B, S, 1024] fp32
    // d_in[1] is H; unused — the transform is computed directly.
    float* out = (float*)d_out;               // [B, S, 1024, 2] fp32

    const int nrows = in_sizes[0] / DIMN;     // 16384

    int sms = 148;
    cudaDeviceGetAttribute(&sms, cudaDevAttrMultiProcessorCount, 0);

    int grid = sms * BPSM;                    // exactly one wave, no tail
    const int max_grid = (nrows + WPB - 1) / WPB;
    if (grid > max_grid) grid = max_grid;

    fwht_kernel<<<grid, 32 * WPB>>>((const float2*)x, (float4*)out, nrows);
}

// round 12
// speedup vs baseline: 1.0031x; 1.0031x over previous
#include <cuda_runtime.h>
#include <cuda_bf16.h>

// Fast Walsh-Hadamard transform, 16384 rows x 1024 fp32.
// y[row] = FWHT(x[row]) / 32, emitted as interleaved (real, 0) pairs.
//
// PERSISTENT pipelined kernel: grid = 6 blocks/SM (exactly one wave, no
// tail). Each warp grid-strides over rows with a 2-deep register pipeline:
// the 16 coalesced LDG.64 for the NEXT row are in flight under the current
// row's ~600-cycle shfl/FADD chain, at every iteration (no pipeline restart).
//
// Per row (one warp, 32 values/thread), lane l owns elements {2l + b + 64j}:
//   stride 1          -> register butterfly (b pair)
//   strides 2..32     -> 5 shfl.xor stages
//   strides 64..512   -> register butterflies over j bits
// No shared memory, no barriers. Stores: 16 coalesced STG.128 (__stcs, so
// the write stream doesn't evict the L2-resident input), zeros folded in.

#define DIMN 1024
#define WPB  4            // warps per block -> 128 threads
#define BPSM 6            // blocks per SM (regs ~80 -> 6*128*80 < 64K regs)

__device__ __forceinline__ void bf(float &x, float &y) {
    float s = x + y;
    y = x - y;
    x = s;
}

__global__ void __launch_bounds__(32 * WPB, BPSM)
fwht_kernel(const float2* __restrict__ xin, float4* __restrict__ yout, int nrows)
{
    const int l  = threadIdx.x & 31;
    const int w  = threadIdx.x >> 5;
    const int gw = blockIdx.x * WPB + w;          // global warp id
    const int stride = gridDim.x * WPB;           // total warps

    int row = gw;
    if (row >= nrows) return;

    // ---- prime the pipeline: 16 independent coalesced LDG.64 ----
    float2 p[16];
    {
        const float2* in = xin + (size_t)row * (DIMN / 2) + l;
        #pragma unroll
        for (int j = 0; j < 16; j++) p[j] = in[32 * j];
    }

    while (true) {
        const int next = row + stride;

        // take ownership of the prefetched row
        float a[16], b[16];
        #pragma unroll
        for (int j = 0; j < 16; j++) { a[j] = p[j].x; b[j] = p[j].y; }

        // issue next row's loads NOW; the compute below hides their latency
        if (next < nrows) {
            const float2* in = xin + (size_t)next * (DIMN / 2) + l;
            #pragma unroll
            for (int j = 0; j < 16; j++) p[j] = in[32 * j];
        }

        // ---- stride 1 (register, b-pair) ----
        #pragma unroll
        for (int j = 0; j < 16; j++) bf(a[j], b[j]);

        // ---- strides 2,4,8,16,32 via shfl.xor on lane bits ----
        #pragma unroll
        for (int d = 1; d <= 16; d <<= 1) {
            const bool up = (l & d) != 0;
            #pragma unroll
            for (int j = 0; j < 16; j++) {
                float oa = __shfl_xor_sync(0xffffffffu, a[j], d);
                float ob = __shfl_xor_sync(0xffffffffu, b[j], d);
                a[j] = up ? (oa - a[j]) : (a[j] + oa);
                b[j] = up ? (ob - b[j]) : (b[j] + ob);
            }
        }

        // ---- strides 64,128,256,512: butterflies over j bits ----
        #pragma unroll
        for (int s = 1; s <= 8; s <<= 1) {
            #pragma unroll
            for (int j = 0; j < 16; j++) {
                if ((j & s) == 0) {
                    bf(a[j], a[j + s]);
                    bf(b[j], b[j + s]);
                }
            }
        }

        // ---- scaled, interleaved (real, 0) stores; 16 coalesced STG.128 ----
        const float sc = 0.03125f;   // 1/sqrt(1024)
        float4* out = yout + (size_t)row * (2 * DIMN / 4) + l;
        #pragma unroll
        for (int j = 0; j < 16; j++) {
            __stcs(out + 32 * j, make_float4(a[j] * sc, 0.0f, b[j] * sc, 0.0f));
        }

        if (next >= nrows) break;
        row = next;
    }
}

extern "C" void kernel_launch(void* const* d_in, const int* in_sizes, int n_in,
                              void* d_out, int out_size)
{
    const float* x = (const float*)d_in[0];   // [B, S, 1024] fp32
    // d_in[1] is H; unused — the transform is computed directly.
    float* out = (float*)d_out;               // [B, S, 1024, 2] fp32

    const int nrows = in_sizes[0] / DIMN;     // 16384

    int sms = 148;
    cudaDeviceGetAttribute(&sms, cudaDevAttrMultiProcessorCount, 0);

    int grid = sms * BPSM;                    // exactly one wave, no tail
    const int max_grid = (nrows + WPB - 1) / WPB;
    if (grid > max_grid) grid = max_grid;

    fwht_kernel<<<grid, 32 * WPB>>>((const float2*)x, (float4*)out, nrows);
}